// round 1
// baseline (speedup 1.0000x reference)
#include <cuda_runtime.h>
#include <math.h>

// ---------------- problem constants ----------------
#define B_SZ    4
#define T_SEQ   2048
#define M_ROWS  (B_SZ * T_SEQ)      // 8192
#define H_DIM   512
#define DFF     2048
#define NHEADS  4
#define DH      128
#define WIN     606
#define NLAYER  4
#define KTRUE   30

// ---------------- device scratch (no allocs allowed) ----------------
__device__ float g_x[M_ROWS * H_DIM];     // activations (ping)
__device__ float g_tmp[M_ROWS * DFF];     // qkv / ff1 / proj scratch
__device__ float g_attn[M_ROWS * H_DIM];  // attention out / misc
__device__ float g_z[M_ROWS * 16];
__device__ float g_yhat[M_ROWS * 8];

__device__ __forceinline__ float gelu_exact(float x) {
    return 0.5f * x * (1.0f + erff(x * 0.70710678118654752f));
}

// ---------------- embedding: u_aug @ W_in + b_in + PE ----------------
__global__ void embed_kernel(const float* __restrict__ u, const float* __restrict__ y,
                             const float* __restrict__ Win, const float* __restrict__ bin,
                             float* __restrict__ x) {
    int row = blockIdx.x;            // b*T + t
    int b = row >> 11, t = row & 2047;
    bool yt = (t < KTRUE);
    float uv[8], yv[8];
#pragma unroll
    for (int c = 0; c < 8; c++) {
        uv[c] = u[((b * 8 + c) << 11) + t];
        yv[c] = yt ? y[((b * 8 + c) << 11) + t] : 0.0f;
    }
    int col = threadIdx.x * 4;       // 128 threads * 4 = 512
#pragma unroll
    for (int j = 0; j < 4; j++) {
        int cj = col + j;
        float s = bin[cj];
#pragma unroll
        for (int c = 0; c < 8; c++) s += uv[c] * Win[c * H_DIM + cj];
        if (yt) {
#pragma unroll
            for (int c = 0; c < 8; c++) s += yv[c] * Win[(16 + c) * H_DIM + cj];
        }
        // positional encoding
        float freq = expf(-(float)(cj & ~1) * (9.210340371976184f / 512.0f));
        float ang = (float)t * freq;
        s += (cj & 1) ? cosf(ang) : sinf(ang);
        x[(size_t)row * H_DIM + cj] = s;
    }
}

// ---------------- generic tiled GEMM: C = act(A[M,K] @ W[K,N] + bias) ----------------
#define BM 64
#define BN 64
#define BK 16

template <int ACT>  // 0 = none, 1 = gelu
__global__ void __launch_bounds__(256) gemm_kernel(
    const float* __restrict__ A, const float* __restrict__ W,
    const float* __restrict__ bias, float* __restrict__ C,
    int M, int N, int K) {
    __shared__ float As[BK][BM + 4];   // stride 68 floats keeps float4 alignment
    __shared__ float Ws[BK][BN];
    int tid = threadIdx.x;
    int row0 = blockIdx.y * BM, col0 = blockIdx.x * BN;
    int tr = tid >> 4, tc = tid & 15;
    int a_m = tid >> 2, a_k = (tid & 3) << 2;
    int w_k = tid >> 4, w_n = (tid & 15) << 2;
    float acc[4][4] = {};

    for (int k0 = 0; k0 < K; k0 += BK) {
        float4 av = *(const float4*)&A[(size_t)(row0 + a_m) * K + k0 + a_k];
        As[a_k + 0][a_m] = av.x;
        As[a_k + 1][a_m] = av.y;
        As[a_k + 2][a_m] = av.z;
        As[a_k + 3][a_m] = av.w;
#pragma unroll
        for (int j = 0; j < 4; j++) {
            int n = col0 + w_n + j;
            Ws[w_k][w_n + j] = (n < N) ? W[(size_t)(k0 + w_k) * N + n] : 0.0f;
        }
        __syncthreads();
#pragma unroll
        for (int kk = 0; kk < BK; kk++) {
            float4 a4 = *(const float4*)&As[kk][tr << 2];
            float4 w4 = *(const float4*)&Ws[kk][tc << 2];
            acc[0][0] += a4.x * w4.x; acc[0][1] += a4.x * w4.y; acc[0][2] += a4.x * w4.z; acc[0][3] += a4.x * w4.w;
            acc[1][0] += a4.y * w4.x; acc[1][1] += a4.y * w4.y; acc[1][2] += a4.y * w4.z; acc[1][3] += a4.y * w4.w;
            acc[2][0] += a4.z * w4.x; acc[2][1] += a4.z * w4.y; acc[2][2] += a4.z * w4.z; acc[2][3] += a4.z * w4.w;
            acc[3][0] += a4.w * w4.x; acc[3][1] += a4.w * w4.y; acc[3][2] += a4.w * w4.z; acc[3][3] += a4.w * w4.w;
        }
        __syncthreads();
    }
#pragma unroll
    for (int i = 0; i < 4; i++) {
        int row = row0 + (tr << 2) + i;
#pragma unroll
        for (int j = 0; j < 4; j++) {
            int cn = col0 + (tc << 2) + j;
            if (cn < N) {
                float v = acc[i][j] + bias[cn];
                if (ACT == 1) v = gelu_exact(v);
                C[(size_t)row * N + cn] = v;
            }
        }
    }
}

// ---------------- sliding-window flash attention ----------------
// qkv: [M, 1536] (q | k | v, each 512 = 4 heads * 128)
// grid: (T/64, NHEADS, B), block 512 threads (16 warps)
// warp w handles queries {w, w+16, w+32, w+48}; lane owns dims lane*4..lane*4+3
#define TQ 64
#define TK 64
#define KST_LD 65
#define ATTN_SMEM_FLOATS (TQ * DH + DH * KST_LD + TK * DH + TQ * TK)

__global__ void __launch_bounds__(512) attn_kernel(const float* __restrict__ qkv,
                                                   float* __restrict__ o) {
    extern __shared__ float sm[];
    float* Qs  = sm;                       // [64][128] (pre-scaled)
    float* KsT = Qs + TQ * DH;             // [128][65] transposed, padded
    float* Vs  = KsT + DH * KST_LD;        // [64][128]
    float* Ss  = Vs + TK * DH;             // [64][64] probs (warp-private rows)

    int tid = threadIdx.x, lane = tid & 31, w = tid >> 5;
    int qt = blockIdx.x, hd = blockIdx.y, b = blockIdx.z;
    int q0 = qt * TQ;
    const float scale = 0.088388347648318447f;  // 1/sqrt(128)
    size_t base = (size_t)(b * T_SEQ) * 1536;

    // load Q (scaled)
    for (int idx = tid; idx < TQ * 32; idx += 512) {
        int r = idx >> 5, c = idx & 31;
        float4 v = *(const float4*)&qkv[base + (size_t)(q0 + r) * 1536 + hd * DH + (c << 2)];
        v.x *= scale; v.y *= scale; v.z *= scale; v.w *= scale;
        *(float4*)&Qs[r * DH + (c << 2)] = v;
    }

    float acc[4][4] = {};
    float mreg[4], lreg[4];
#pragma unroll
    for (int r = 0; r < 4; r++) { mreg[r] = -1e30f; lreg[r] = 0.0f; }

    int lo = q0 - (WIN - 1);
    if (lo < 0) lo = 0;
    for (int kt = lo >> 6; kt <= qt; kt++) {
        int k0 = kt * TK;
        __syncthreads();  // prior tile fully consumed (also covers Q load, iter 0)
        for (int idx = tid; idx < TK * 32; idx += 512) {
            int r = idx >> 5, c = idx & 31;
            size_t rb = base + (size_t)(k0 + r) * 1536 + hd * DH + (c << 2);
            float4 kv = *(const float4*)&qkv[rb + 512];
            float4 vv = *(const float4*)&qkv[rb + 1024];
            int d = c << 2;
            KsT[(d + 0) * KST_LD + r] = kv.x;
            KsT[(d + 1) * KST_LD + r] = kv.y;
            KsT[(d + 2) * KST_LD + r] = kv.z;
            KsT[(d + 3) * KST_LD + r] = kv.w;
            *(float4*)&Vs[r * DH + d] = vv;
        }
        __syncthreads();

        // S = Q K^T for this warp's 4 query rows; lane covers keys {lane, lane+32}
        float s0[4] = {0, 0, 0, 0}, s1[4] = {0, 0, 0, 0};
        for (int d0 = 0; d0 < DH; d0 += 4) {
            float ka[4], kb[4];
#pragma unroll
            for (int j = 0; j < 4; j++) {
                ka[j] = KsT[(d0 + j) * KST_LD + lane];
                kb[j] = KsT[(d0 + j) * KST_LD + lane + 32];
            }
#pragma unroll
            for (int r = 0; r < 4; r++) {
                float4 q4 = *(const float4*)&Qs[(w + (r << 4)) * DH + d0];
                s0[r] += q4.x * ka[0] + q4.y * ka[1] + q4.z * ka[2] + q4.w * ka[3];
                s1[r] += q4.x * kb[0] + q4.y * kb[1] + q4.z * kb[2] + q4.w * kb[3];
            }
        }
        // mask + online softmax (warp-private)
#pragma unroll
        for (int r = 0; r < 4; r++) {
            int i = q0 + w + (r << 4);
            int j0 = k0 + lane, j1 = j0 + 32;
            if (!(j0 <= i && j0 > i - WIN)) s0[r] = -1e30f;
            if (!(j1 <= i && j1 > i - WIN)) s1[r] = -1e30f;
            float mt = fmaxf(s0[r], s1[r]);
#pragma unroll
            for (int off = 16; off; off >>= 1) mt = fmaxf(mt, __shfl_xor_sync(0xffffffffu, mt, off));
            float mnew = fmaxf(mreg[r], mt);
            float p0 = (s0[r] > -1e29f) ? expf(s0[r] - mnew) : 0.0f;
            float p1 = (s1[r] > -1e29f) ? expf(s1[r] - mnew) : 0.0f;
            float rs = p0 + p1;
#pragma unroll
            for (int off = 16; off; off >>= 1) rs += __shfl_xor_sync(0xffffffffu, rs, off);
            float sc = expf(mreg[r] - mnew);
            lreg[r] = lreg[r] * sc + rs;
            mreg[r] = mnew;
#pragma unroll
            for (int j = 0; j < 4; j++) acc[r][j] *= sc;
            Ss[(w + (r << 4)) * TK + lane] = p0;
            Ss[(w + (r << 4)) * TK + lane + 32] = p1;
        }
        __syncwarp();
        // acc += P @ V
        for (int k = 0; k < TK; k++) {
            float4 v4 = *(const float4*)&Vs[k * DH + (lane << 2)];
#pragma unroll
            for (int r = 0; r < 4; r++) {
                float p = Ss[(w + (r << 4)) * TK + k];
                acc[r][0] += p * v4.x; acc[r][1] += p * v4.y;
                acc[r][2] += p * v4.z; acc[r][3] += p * v4.w;
            }
        }
        __syncwarp();
    }
#pragma unroll
    for (int r = 0; r < 4; r++) {
        float inv = 1.0f / lreg[r];
        int row = q0 + w + (r << 4);
        float4 ov;
        ov.x = acc[r][0] * inv; ov.y = acc[r][1] * inv;
        ov.z = acc[r][2] * inv; ov.w = acc[r][3] * inv;
        *(float4*)&o[(size_t)(b * T_SEQ + row) * H_DIM + hd * DH + (lane << 2)] = ov;
    }
}

// ---------------- residual + layernorm (in place on x) ----------------
__global__ void resid_ln_kernel(float* __restrict__ x, const float* __restrict__ p,
                                const float* __restrict__ g, const float* __restrict__ bb,
                                int has_res) {
    __shared__ float red[8];
    int row = blockIdx.x, tid = threadIdx.x;  // 128 threads
    int c = tid * 4;
    float4 v = *(float4*)&x[(size_t)row * H_DIM + c];
    if (has_res) {
        float4 pv = *(const float4*)&p[(size_t)row * H_DIM + c];
        v.x += pv.x; v.y += pv.y; v.z += pv.z; v.w += pv.w;
    }
    float s = v.x + v.y + v.z + v.w;
    float q = v.x * v.x + v.y * v.y + v.z * v.z + v.w * v.w;
    int lane = tid & 31, wp = tid >> 5;
#pragma unroll
    for (int off = 16; off; off >>= 1) s += __shfl_xor_sync(0xffffffffu, s, off);
    if (lane == 0) red[wp] = s;
    __syncthreads();
    float s_tot = red[0] + red[1] + red[2] + red[3];
    __syncthreads();
#pragma unroll
    for (int off = 16; off; off >>= 1) q += __shfl_xor_sync(0xffffffffu, q, off);
    if (lane == 0) red[wp] = q;
    __syncthreads();
    float q_tot = red[0] + red[1] + red[2] + red[3];

    float mean = s_tot * (1.0f / 512.0f);
    float var = q_tot * (1.0f / 512.0f) - mean * mean;
    float inv = rsqrtf(var + 1e-5f);
    float4 ov;
    ov.x = (v.x - mean) * inv * g[c + 0] + bb[c + 0];
    ov.y = (v.y - mean) * inv * g[c + 1] + bb[c + 1];
    ov.z = (v.z - mean) * inv * g[c + 2] + bb[c + 2];
    ov.w = (v.w - mean) * inv * g[c + 3] + bb[c + 3];
    *(float4*)&x[(size_t)row * H_DIM + c] = ov;
}

// ---------------- loss ----------------
__global__ void zero_kernel(float* o) { o[0] = 0.0f; }

__global__ void loss_kernel(const float* __restrict__ yhat, const float* __restrict__ y,
                            float* __restrict__ o) {
    __shared__ float red[8];
    int tid = threadIdx.x;
    float s = 0.0f;
    for (int idx = blockIdx.x * 256 + tid; idx < M_ROWS * 8; idx += gridDim.x * 256) {
        int row = idx >> 3, c = idx & 7;
        int b = row >> 11, t = row & 2047;
        float d = yhat[idx] - y[((b * 8 + c) << 11) + t];
        s += d * d;
    }
    int lane = tid & 31, wp = tid >> 5;
#pragma unroll
    for (int off = 16; off; off >>= 1) s += __shfl_xor_sync(0xffffffffu, s, off);
    if (lane == 0) red[wp] = s;
    __syncthreads();
    if (tid == 0) {
        float t2 = 0.0f;
        for (int i = 0; i < 8; i++) t2 += red[i];
        atomicAdd(o, t2);
    }
}

// ---------------- launch ----------------
extern "C" void kernel_launch(void* const* d_in, const int* in_sizes, int n_in,
                              void* d_out, int out_size) {
    const float* u     = (const float*)d_in[0];
    const float* y     = (const float*)d_in[1];
    const float* W_in  = (const float*)d_in[2];
    const float* b_in  = (const float*)d_in[3];
    const float* qkv_w = (const float*)d_in[4];
    const float* qkv_b = (const float*)d_in[5];
    const float* out_w = (const float*)d_in[6];
    const float* out_b = (const float*)d_in[7];
    const float* ff1_w = (const float*)d_in[8];
    const float* ff1_b = (const float*)d_in[9];
    const float* ff2_w = (const float*)d_in[10];
    const float* ff2_b = (const float*)d_in[11];
    const float* ln1_g = (const float*)d_in[12];
    const float* ln1_b = (const float*)d_in[13];
    const float* ln2_g = (const float*)d_in[14];
    const float* ln2_b = (const float*)d_in[15];
    const float* lnf_g = (const float*)d_in[16];
    const float* lnf_b = (const float*)d_in[17];
    const float* xm1_w = (const float*)d_in[18];
    const float* xm1_b = (const float*)d_in[19];
    const float* xm2_w = (const float*)d_in[20];
    const float* xm2_b = (const float*)d_in[21];
    const float* me1_w = (const float*)d_in[22];
    const float* me1_b = (const float*)d_in[23];
    const float* me2_w = (const float*)d_in[24];
    const float* me2_b = (const float*)d_in[25];
    const float* me3_w = (const float*)d_in[26];
    const float* me3_b = (const float*)d_in[27];

    float *xb, *tb, *ab, *zb, *yb;
    cudaGetSymbolAddress((void**)&xb, g_x);
    cudaGetSymbolAddress((void**)&tb, g_tmp);
    cudaGetSymbolAddress((void**)&ab, g_attn);
    cudaGetSymbolAddress((void**)&zb, g_z);
    cudaGetSymbolAddress((void**)&yb, g_yhat);

    const int ATTN_SMEM = ATTN_SMEM_FLOATS * (int)sizeof(float);  // 115200 B
    cudaFuncSetAttribute(attn_kernel, cudaFuncAttributeMaxDynamicSharedMemorySize, ATTN_SMEM);

    embed_kernel<<<M_ROWS, 128>>>(u, y, W_in, b_in, xb);

    for (int l = 0; l < NLAYER; l++) {
        gemm_kernel<0><<<dim3(1536 / BN, M_ROWS / BM), 256>>>(
            xb, qkv_w + (size_t)l * 512 * 1536, qkv_b + (size_t)l * 1536, tb,
            M_ROWS, 1536, 512);
        attn_kernel<<<dim3(T_SEQ / TQ, NHEADS, B_SZ), 512, ATTN_SMEM>>>(tb, ab);
        gemm_kernel<0><<<dim3(512 / BN, M_ROWS / BM), 256>>>(
            ab, out_w + (size_t)l * 512 * 512, out_b + (size_t)l * 512, tb,
            M_ROWS, 512, 512);
        resid_ln_kernel<<<M_ROWS, 128>>>(xb, tb, ln1_g + l * 512, ln1_b + l * 512, 1);
        gemm_kernel<1><<<dim3(2048 / BN, M_ROWS / BM), 256>>>(
            xb, ff1_w + (size_t)l * 512 * 2048, ff1_b + (size_t)l * 2048, tb,
            M_ROWS, 2048, 512);
        gemm_kernel<0><<<dim3(512 / BN, M_ROWS / BM), 256>>>(
            tb, ff2_w + (size_t)l * 2048 * 512, ff2_b + (size_t)l * 512, ab,
            M_ROWS, 512, 2048);
        resid_ln_kernel<<<M_ROWS, 128>>>(xb, ab, ln2_g + l * 512, ln2_b + l * 512, 1);
    }
    resid_ln_kernel<<<M_ROWS, 128>>>(xb, nullptr, lnf_g, lnf_b, 0);

    gemm_kernel<1><<<dim3(512 / BN, M_ROWS / BM), 256>>>(xb, xm1_w, xm1_b, ab, M_ROWS, 512, 512);
    gemm_kernel<0><<<dim3(1, M_ROWS / BM), 256>>>(ab, xm2_w, xm2_b, zb, M_ROWS, 16, 512);
    gemm_kernel<1><<<dim3(512 / BN, M_ROWS / BM), 256>>>(zb, me1_w, me1_b, ab, M_ROWS, 512, 16);
    gemm_kernel<1><<<dim3(512 / BN, M_ROWS / BM), 256>>>(ab, me2_w, me2_b, tb, M_ROWS, 512, 512);
    gemm_kernel<0><<<dim3(1, M_ROWS / BM), 256>>>(tb, me3_w, me3_b, yb, M_ROWS, 8, 512);

    zero_kernel<<<1, 1>>>((float*)d_out);
    loss_kernel<<<64, 256>>>(yb, y, (float*)d_out);
}

// round 4
// speedup vs baseline: 2.8064x; 2.8064x over previous
#include <cuda_runtime.h>
#include <math.h>

// ---------------- problem constants ----------------
#define B_SZ    4
#define T_SEQ   2048
#define M_ROWS  (B_SZ * T_SEQ)      // 8192
#define H_DIM   512
#define DFF     2048
#define NHEADS  4
#define DH      128
#define WIN     606
#define NLAYER  4
#define KTRUE   30

// ---------------- device scratch (no allocs allowed) ----------------
__device__ float g_x[M_ROWS * H_DIM];
__device__ float g_tmp[M_ROWS * DFF];
__device__ float g_attn[M_ROWS * H_DIM];
__device__ float g_z[M_ROWS * 16];
__device__ float g_yhat[M_ROWS * 8];

__device__ __forceinline__ float gelu_exact(float x) {
    return 0.5f * x * (1.0f + erff(x * 0.70710678118654752f));
}

// pack two fp32 into bf16x2 (round-to-nearest-even), pure integer math
__device__ __forceinline__ unsigned pk(float x, float y) {
    unsigned ux = __float_as_uint(x);
    unsigned uy = __float_as_uint(y);
    unsigned lo = (ux + 0x7FFFu + ((ux >> 16) & 1u)) >> 16;
    unsigned hi = (uy + 0x7FFFu + ((uy >> 16) & 1u)) >> 16;
    return lo | (hi << 16);
}

// ---------------- embedding ----------------
__global__ void embed_kernel(const float* __restrict__ u, const float* __restrict__ y,
                             const float* __restrict__ Win, const float* __restrict__ bin,
                             float* __restrict__ x) {
    int row = blockIdx.x;
    int b = row >> 11, t = row & 2047;
    bool yt = (t < KTRUE);
    float uv[8], yv[8];
#pragma unroll
    for (int c = 0; c < 8; c++) {
        uv[c] = u[((b * 8 + c) << 11) + t];
        yv[c] = yt ? y[((b * 8 + c) << 11) + t] : 0.0f;
    }
    int col = threadIdx.x * 4;
#pragma unroll
    for (int j = 0; j < 4; j++) {
        int cj = col + j;
        float s = bin[cj];
#pragma unroll
        for (int c = 0; c < 8; c++) s += uv[c] * Win[c * H_DIM + cj];
        if (yt) {
#pragma unroll
            for (int c = 0; c < 8; c++) s += yv[c] * Win[(16 + c) * H_DIM + cj];
        }
        float freq = expf(-(float)(cj & ~1) * (9.210340371976184f / 512.0f));
        float ang = (float)t * freq;
        s += (cj & 1) ? cosf(ang) : sinf(ang);
        x[(size_t)row * H_DIM + cj] = s;
    }
}

// ---------------- fp32 GEMM (small N / small K cases) ----------------
#define BM 64
#define BN 64
#define BK 16

template <int ACT>
__global__ void __launch_bounds__(256) gemm_kernel(
    const float* __restrict__ A, const float* __restrict__ W,
    const float* __restrict__ bias, float* __restrict__ C,
    int M, int N, int K) {
    __shared__ float As[BK][BM + 4];
    __shared__ float Ws[BK][BN];
    int tid = threadIdx.x;
    int row0 = blockIdx.y * BM, col0 = blockIdx.x * BN;
    int tr = tid >> 4, tc = tid & 15;
    int a_m = tid >> 2, a_k = (tid & 3) << 2;
    int w_k = tid >> 4, w_n = (tid & 15) << 2;
    float acc[4][4] = {};

    for (int k0 = 0; k0 < K; k0 += BK) {
        float4 av = *(const float4*)&A[(size_t)(row0 + a_m) * K + k0 + a_k];
        As[a_k + 0][a_m] = av.x;
        As[a_k + 1][a_m] = av.y;
        As[a_k + 2][a_m] = av.z;
        As[a_k + 3][a_m] = av.w;
#pragma unroll
        for (int j = 0; j < 4; j++) {
            int n = col0 + w_n + j;
            Ws[w_k][w_n + j] = (n < N) ? W[(size_t)(k0 + w_k) * N + n] : 0.0f;
        }
        __syncthreads();
#pragma unroll
        for (int kk = 0; kk < BK; kk++) {
            float4 a4 = *(const float4*)&As[kk][tr << 2];
            float4 w4 = *(const float4*)&Ws[kk][tc << 2];
            acc[0][0] += a4.x * w4.x; acc[0][1] += a4.x * w4.y; acc[0][2] += a4.x * w4.z; acc[0][3] += a4.x * w4.w;
            acc[1][0] += a4.y * w4.x; acc[1][1] += a4.y * w4.y; acc[1][2] += a4.y * w4.z; acc[1][3] += a4.y * w4.w;
            acc[2][0] += a4.z * w4.x; acc[2][1] += a4.z * w4.y; acc[2][2] += a4.z * w4.z; acc[2][3] += a4.z * w4.w;
            acc[3][0] += a4.w * w4.x; acc[3][1] += a4.w * w4.y; acc[3][2] += a4.w * w4.z; acc[3][3] += a4.w * w4.w;
        }
        __syncthreads();
    }
#pragma unroll
    for (int i = 0; i < 4; i++) {
        int row = row0 + (tr << 2) + i;
#pragma unroll
        for (int j = 0; j < 4; j++) {
            int cn = col0 + (tc << 2) + j;
            if (cn < N) {
                float v = acc[i][j] + bias[cn];
                if (ACT == 1) v = gelu_exact(v);
                C[(size_t)row * N + cn] = v;
            }
        }
    }
}

// ---------------- bf16 tensor-core GEMM ----------------
// C[M,N] = act(A[M,K] @ W[K,N] + bias); M%128==0, N%128==0, K%32==0.
// CTA 128x128x32, 8 warps (2x4), warp tile 64x32, mma.m16n8k16 bf16->fp32.
#define BM2 128
#define BN2 128
#define BK2 32
#define A_LD 40
#define B_LD 136

__device__ __forceinline__ unsigned smem_u32(const void* p) {
    unsigned a;
    asm("{ .reg .u64 t; cvta.to.shared.u64 t, %1; cvt.u32.u64 %0, t; }" : "=r"(a) : "l"(p));
    return a;
}
__device__ __forceinline__ void ldsm4(unsigned* r, unsigned addr) {
    asm volatile("ldmatrix.sync.aligned.m8n8.x4.shared.b16 {%0,%1,%2,%3}, [%4];"
                 : "=r"(r[0]), "=r"(r[1]), "=r"(r[2]), "=r"(r[3]) : "r"(addr));
}
__device__ __forceinline__ void ldsm4t(unsigned* r, unsigned addr) {
    asm volatile("ldmatrix.sync.aligned.m8n8.x4.trans.shared.b16 {%0,%1,%2,%3}, [%4];"
                 : "=r"(r[0]), "=r"(r[1]), "=r"(r[2]), "=r"(r[3]) : "r"(addr));
}
__device__ __forceinline__ void mma16816(float* d, const unsigned* a, const unsigned* b) {
    asm volatile(
        "mma.sync.aligned.m16n8k16.row.col.f32.bf16.bf16.f32 "
        "{%0,%1,%2,%3}, {%4,%5,%6,%7}, {%8,%9}, {%0,%1,%2,%3};"
        : "+f"(d[0]), "+f"(d[1]), "+f"(d[2]), "+f"(d[3])
        : "r"(a[0]), "r"(a[1]), "r"(a[2]), "r"(a[3]), "r"(b[0]), "r"(b[1]));
}

template <int ACT>
__global__ void __launch_bounds__(256) mma_gemm(
    const float* __restrict__ A, const float* __restrict__ W,
    const float* __restrict__ bias, float* __restrict__ C,
    int M, int N, int K) {
    __shared__ unsigned short As[2][BM2 * A_LD];
    __shared__ unsigned short Bs[2][BK2 * B_LD];
    int tid = threadIdx.x, lane = tid & 31, w = tid >> 5;
    int wm = (w & 1) * 64, wn = (w >> 1) * 32;
    int row0 = blockIdx.y * BM2, col0 = blockIdx.x * BN2;

    int aRow = tid >> 3, aK = (tid & 7) << 2;     // A: rows aRow+32j, 4 floats at aK
    int bRow = tid >> 5, bCol = (tid & 31) << 2;  // B: rows bRow+8j, 4 floats at bCol

    float acc[4][4][4];
#pragma unroll
    for (int i = 0; i < 4; i++)
#pragma unroll
        for (int j = 0; j < 4; j++)
#pragma unroll
            for (int k = 0; k < 4; k++) acc[i][j][k] = 0.0f;

    uint2 aReg[4], bReg[4];
    int ktiles = K / BK2;

    // prologue: global load for kt=0
    {
        const float* Ab = A + (size_t)row0 * K + aK;
        const float* Wb = W + col0 + bCol;
#pragma unroll
        for (int j = 0; j < 4; j++) {
            float4 v = *(const float4*)(Ab + (size_t)(aRow + 32 * j) * K);
            aReg[j].x = pk(v.x, v.y);
            aReg[j].y = pk(v.z, v.w);
        }
#pragma unroll
        for (int j = 0; j < 4; j++) {
            float4 v = *(const float4*)(Wb + (size_t)(bRow + 8 * j) * N);
            bReg[j].x = pk(v.x, v.y);
            bReg[j].y = pk(v.z, v.w);
        }
    }
#pragma unroll
    for (int j = 0; j < 4; j++)
        *(uint2*)&As[0][(aRow + 32 * j) * A_LD + aK] = aReg[j];
#pragma unroll
    for (int j = 0; j < 4; j++)
        *(uint2*)&Bs[0][(bRow + 8 * j) * B_LD + bCol] = bReg[j];
    __syncthreads();

    for (int kt = 0; kt < ktiles; kt++) {
        int s = kt & 1;
        if (kt + 1 < ktiles) {
            const float* Ab = A + (size_t)row0 * K + (kt + 1) * BK2 + aK;
            const float* Wb = W + (size_t)((kt + 1) * BK2) * N + col0 + bCol;
#pragma unroll
            for (int j = 0; j < 4; j++) {
                float4 v = *(const float4*)(Ab + (size_t)(aRow + 32 * j) * K);
                aReg[j].x = pk(v.x, v.y);
                aReg[j].y = pk(v.z, v.w);
            }
#pragma unroll
            for (int j = 0; j < 4; j++) {
                float4 v = *(const float4*)(Wb + (size_t)(bRow + 8 * j) * N);
                bReg[j].x = pk(v.x, v.y);
                bReg[j].y = pk(v.z, v.w);
            }
        }
        unsigned aBase = smem_u32(&As[s][0]);
        unsigned bBase = smem_u32(&Bs[s][0]);
#pragma unroll
        for (int ks = 0; ks < 2; ks++) {
            unsigned af[4][4];
#pragma unroll
            for (int mt = 0; mt < 4; mt++)
                ldsm4(af[mt], aBase + 2u * (unsigned)((wm + mt * 16 + (lane & 15)) * A_LD +
                                                      ks * 16 + (lane >> 4) * 8));
            unsigned bf[2][4];
#pragma unroll
            for (int nb = 0; nb < 2; nb++)
                ldsm4t(bf[nb], bBase + 2u * (unsigned)((ks * 16 + (lane & 15)) * B_LD +
                                                       wn + nb * 16 + (lane >> 4) * 8));
#pragma unroll
            for (int mt = 0; mt < 4; mt++) {
#pragma unroll
                for (int nt = 0; nt < 4; nt++) {
                    unsigned bb[2];
                    bb[0] = bf[nt >> 1][(nt & 1) * 2];
                    bb[1] = bf[nt >> 1][(nt & 1) * 2 + 1];
                    mma16816(acc[mt][nt], af[mt], bb);
                }
            }
        }
        __syncthreads();
        if (kt + 1 < ktiles) {
#pragma unroll
            for (int j = 0; j < 4; j++)
                *(uint2*)&As[1 - s][(aRow + 32 * j) * A_LD + aK] = aReg[j];
#pragma unroll
            for (int j = 0; j < 4; j++)
                *(uint2*)&Bs[1 - s][(bRow + 8 * j) * B_LD + bCol] = bReg[j];
            __syncthreads();
        }
    }

    // epilogue
#pragma unroll
    for (int mt = 0; mt < 4; mt++) {
#pragma unroll
        for (int nt = 0; nt < 4; nt++) {
            int r = row0 + wm + mt * 16 + (lane >> 2);
            int c = col0 + wn + nt * 8 + (lane & 3) * 2;
            float b0 = bias[c], b1 = bias[c + 1];
            float v0 = acc[mt][nt][0] + b0, v1 = acc[mt][nt][1] + b1;
            float v2 = acc[mt][nt][2] + b0, v3 = acc[mt][nt][3] + b1;
            if (ACT == 1) {
                v0 = gelu_exact(v0); v1 = gelu_exact(v1);
                v2 = gelu_exact(v2); v3 = gelu_exact(v3);
            }
            *(float2*)&C[(size_t)r * N + c] = make_float2(v0, v1);
            *(float2*)&C[(size_t)(r + 8) * N + c] = make_float2(v2, v3);
        }
    }
}

// ---------------- sliding-window flash attention (fp32) ----------------
#define TQ 64
#define TK 64
#define KST_LD 65
#define ATTN_SMEM_FLOATS (TQ * DH + DH * KST_LD + TK * DH + TQ * TK)

__global__ void __launch_bounds__(512) attn_kernel(const float* __restrict__ qkv,
                                                   float* __restrict__ o) {
    extern __shared__ float sm[];
    float* Qs  = sm;
    float* KsT = Qs + TQ * DH;
    float* Vs  = KsT + DH * KST_LD;
    float* Ss  = Vs + TK * DH;

    int tid = threadIdx.x, lane = tid & 31, w = tid >> 5;
    int qt = blockIdx.x, hd = blockIdx.y, b = blockIdx.z;
    int q0 = qt * TQ;
    const float scale = 0.088388347648318447f;
    size_t base = (size_t)(b * T_SEQ) * 1536;

    for (int idx = tid; idx < TQ * 32; idx += 512) {
        int r = idx >> 5, c = idx & 31;
        float4 v = *(const float4*)&qkv[base + (size_t)(q0 + r) * 1536 + hd * DH + (c << 2)];
        v.x *= scale; v.y *= scale; v.z *= scale; v.w *= scale;
        *(float4*)&Qs[r * DH + (c << 2)] = v;
    }

    float acc[4][4] = {};
    float mreg[4], lreg[4];
#pragma unroll
    for (int r = 0; r < 4; r++) { mreg[r] = -1e30f; lreg[r] = 0.0f; }

    int lo = q0 - (WIN - 1);
    if (lo < 0) lo = 0;
    for (int kt = lo >> 6; kt <= qt; kt++) {
        int k0 = kt * TK;
        __syncthreads();
        for (int idx = tid; idx < TK * 32; idx += 512) {
            int r = idx >> 5, c = idx & 31;
            size_t rb = base + (size_t)(k0 + r) * 1536 + hd * DH + (c << 2);
            float4 kv = *(const float4*)&qkv[rb + 512];
            float4 vv = *(const float4*)&qkv[rb + 1024];
            int d = c << 2;
            KsT[(d + 0) * KST_LD + r] = kv.x;
            KsT[(d + 1) * KST_LD + r] = kv.y;
            KsT[(d + 2) * KST_LD + r] = kv.z;
            KsT[(d + 3) * KST_LD + r] = kv.w;
            *(float4*)&Vs[r * DH + d] = vv;
        }
        __syncthreads();

        float s0[4] = {0, 0, 0, 0}, s1[4] = {0, 0, 0, 0};
        for (int d0 = 0; d0 < DH; d0 += 4) {
            float ka[4], kb[4];
#pragma unroll
            for (int j = 0; j < 4; j++) {
                ka[j] = KsT[(d0 + j) * KST_LD + lane];
                kb[j] = KsT[(d0 + j) * KST_LD + lane + 32];
            }
#pragma unroll
            for (int r = 0; r < 4; r++) {
                float4 q4 = *(const float4*)&Qs[(w + (r << 4)) * DH + d0];
                s0[r] += q4.x * ka[0] + q4.y * ka[1] + q4.z * ka[2] + q4.w * ka[3];
                s1[r] += q4.x * kb[0] + q4.y * kb[1] + q4.z * kb[2] + q4.w * kb[3];
            }
        }
#pragma unroll
        for (int r = 0; r < 4; r++) {
            int i = q0 + w + (r << 4);
            int j0 = k0 + lane, j1 = j0 + 32;
            if (!(j0 <= i && j0 > i - WIN)) s0[r] = -1e30f;
            if (!(j1 <= i && j1 > i - WIN)) s1[r] = -1e30f;
            float mt = fmaxf(s0[r], s1[r]);
#pragma unroll
            for (int off = 16; off; off >>= 1) mt = fmaxf(mt, __shfl_xor_sync(0xffffffffu, mt, off));
            float mnew = fmaxf(mreg[r], mt);
            float p0 = (s0[r] > -1e29f) ? expf(s0[r] - mnew) : 0.0f;
            float p1 = (s1[r] > -1e29f) ? expf(s1[r] - mnew) : 0.0f;
            float rs = p0 + p1;
#pragma unroll
            for (int off = 16; off; off >>= 1) rs += __shfl_xor_sync(0xffffffffu, rs, off);
            float sc = expf(mreg[r] - mnew);
            lreg[r] = lreg[r] * sc + rs;
            mreg[r] = mnew;
#pragma unroll
            for (int j = 0; j < 4; j++) acc[r][j] *= sc;
            Ss[(w + (r << 4)) * TK + lane] = p0;
            Ss[(w + (r << 4)) * TK + lane + 32] = p1;
        }
        __syncwarp();
        for (int k = 0; k < TK; k++) {
            float4 v4 = *(const float4*)&Vs[k * DH + (lane << 2)];
#pragma unroll
            for (int r = 0; r < 4; r++) {
                float p = Ss[(w + (r << 4)) * TK + k];
                acc[r][0] += p * v4.x; acc[r][1] += p * v4.y;
                acc[r][2] += p * v4.z; acc[r][3] += p * v4.w;
            }
        }
        __syncwarp();
    }
#pragma unroll
    for (int r = 0; r < 4; r++) {
        float inv = 1.0f / lreg[r];
        int row = q0 + w + (r << 4);
        float4 ov;
        ov.x = acc[r][0] * inv; ov.y = acc[r][1] * inv;
        ov.z = acc[r][2] * inv; ov.w = acc[r][3] * inv;
        *(float4*)&o[(size_t)(b * T_SEQ + row) * H_DIM + hd * DH + (lane << 2)] = ov;
    }
}

// ---------------- residual + layernorm ----------------
__global__ void resid_ln_kernel(float* __restrict__ x, const float* __restrict__ p,
                                const float* __restrict__ g, const float* __restrict__ bb,
                                int has_res) {
    __shared__ float red[8];
    int row = blockIdx.x, tid = threadIdx.x;
    int c = tid * 4;
    float4 v = *(float4*)&x[(size_t)row * H_DIM + c];
    if (has_res) {
        float4 pv = *(const float4*)&p[(size_t)row * H_DIM + c];
        v.x += pv.x; v.y += pv.y; v.z += pv.z; v.w += pv.w;
    }
    float s = v.x + v.y + v.z + v.w;
    float q = v.x * v.x + v.y * v.y + v.z * v.z + v.w * v.w;
    int lane = tid & 31, wp = tid >> 5;
#pragma unroll
    for (int off = 16; off; off >>= 1) s += __shfl_xor_sync(0xffffffffu, s, off);
    if (lane == 0) red[wp] = s;
    __syncthreads();
    float s_tot = red[0] + red[1] + red[2] + red[3];
    __syncthreads();
#pragma unroll
    for (int off = 16; off; off >>= 1) q += __shfl_xor_sync(0xffffffffu, q, off);
    if (lane == 0) red[wp] = q;
    __syncthreads();
    float q_tot = red[0] + red[1] + red[2] + red[3];

    float mean = s_tot * (1.0f / 512.0f);
    float var = q_tot * (1.0f / 512.0f) - mean * mean;
    float inv = rsqrtf(var + 1e-5f);
    float4 ov;
    ov.x = (v.x - mean) * inv * g[c + 0] + bb[c + 0];
    ov.y = (v.y - mean) * inv * g[c + 1] + bb[c + 1];
    ov.z = (v.z - mean) * inv * g[c + 2] + bb[c + 2];
    ov.w = (v.w - mean) * inv * g[c + 3] + bb[c + 3];
    *(float4*)&x[(size_t)row * H_DIM + c] = ov;
}

// ---------------- loss ----------------
__global__ void zero_kernel(float* o) { o[0] = 0.0f; }

__global__ void loss_kernel(const float* __restrict__ yhat, const float* __restrict__ y,
                            float* __restrict__ o) {
    __shared__ float red[8];
    int tid = threadIdx.x;
    float s = 0.0f;
    for (int idx = blockIdx.x * 256 + tid; idx < M_ROWS * 8; idx += gridDim.x * 256) {
        int row = idx >> 3, c = idx & 7;
        int b = row >> 11, t = row & 2047;
        float d = yhat[idx] - y[((b * 8 + c) << 11) + t];
        s += d * d;
    }
    int lane = tid & 31, wp = tid >> 5;
#pragma unroll
    for (int off = 16; off; off >>= 1) s += __shfl_xor_sync(0xffffffffu, s, off);
    if (lane == 0) red[wp] = s;
    __syncthreads();
    if (tid == 0) {
        float t2 = 0.0f;
        for (int i = 0; i < 8; i++) t2 += red[i];
        atomicAdd(o, t2);
    }
}

// ---------------- launch ----------------
extern "C" void kernel_launch(void* const* d_in, const int* in_sizes, int n_in,
                              void* d_out, int out_size) {
    const float* u     = (const float*)d_in[0];
    const float* y     = (const float*)d_in[1];
    const float* W_in  = (const float*)d_in[2];
    const float* b_in  = (const float*)d_in[3];
    const float* qkv_w = (const float*)d_in[4];
    const float* qkv_b = (const float*)d_in[5];
    const float* out_w = (const float*)d_in[6];
    const float* out_b = (const float*)d_in[7];
    const float* ff1_w = (const float*)d_in[8];
    const float* ff1_b = (const float*)d_in[9];
    const float* ff2_w = (const float*)d_in[10];
    const float* ff2_b = (const float*)d_in[11];
    const float* ln1_g = (const float*)d_in[12];
    const float* ln1_b = (const float*)d_in[13];
    const float* ln2_g = (const float*)d_in[14];
    const float* ln2_b = (const float*)d_in[15];
    const float* lnf_g = (const float*)d_in[16];
    const float* lnf_b = (const float*)d_in[17];
    const float* xm1_w = (const float*)d_in[18];
    const float* xm1_b = (const float*)d_in[19];
    const float* xm2_w = (const float*)d_in[20];
    const float* xm2_b = (const float*)d_in[21];
    const float* me1_w = (const float*)d_in[22];
    const float* me1_b = (const float*)d_in[23];
    const float* me2_w = (const float*)d_in[24];
    const float* me2_b = (const float*)d_in[25];
    const float* me3_w = (const float*)d_in[26];
    const float* me3_b = (const float*)d_in[27];

    float *xb, *tb, *ab, *zb, *yb;
    cudaGetSymbolAddress((void**)&xb, g_x);
    cudaGetSymbolAddress((void**)&tb, g_tmp);
    cudaGetSymbolAddress((void**)&ab, g_attn);
    cudaGetSymbolAddress((void**)&zb, g_z);
    cudaGetSymbolAddress((void**)&yb, g_yhat);

    const int ATTN_SMEM = ATTN_SMEM_FLOATS * (int)sizeof(float);
    cudaFuncSetAttribute(attn_kernel, cudaFuncAttributeMaxDynamicSharedMemorySize, ATTN_SMEM);

    embed_kernel<<<M_ROWS, 128>>>(u, y, W_in, b_in, xb);

    for (int l = 0; l < NLAYER; l++) {
        mma_gemm<0><<<dim3(1536 / BN2, M_ROWS / BM2), 256>>>(
            xb, qkv_w + (size_t)l * 512 * 1536, qkv_b + (size_t)l * 1536, tb,
            M_ROWS, 1536, 512);
        attn_kernel<<<dim3(T_SEQ / TQ, NHEADS, B_SZ), 512, ATTN_SMEM>>>(tb, ab);
        mma_gemm<0><<<dim3(512 / BN2, M_ROWS / BM2), 256>>>(
            ab, out_w + (size_t)l * 512 * 512, out_b + (size_t)l * 512, tb,
            M_ROWS, 512, 512);
        resid_ln_kernel<<<M_ROWS, 128>>>(xb, tb, ln1_g + l * 512, ln1_b + l * 512, 1);
        mma_gemm<1><<<dim3(2048 / BN2, M_ROWS / BM2), 256>>>(
            xb, ff1_w + (size_t)l * 512 * 2048, ff1_b + (size_t)l * 2048, tb,
            M_ROWS, 2048, 512);
        mma_gemm<0><<<dim3(512 / BN2, M_ROWS / BM2), 256>>>(
            tb, ff2_w + (size_t)l * 2048 * 512, ff2_b + (size_t)l * 512, ab,
            M_ROWS, 512, 2048);
        resid_ln_kernel<<<M_ROWS, 128>>>(xb, ab, ln2_g + l * 512, ln2_b + l * 512, 1);
    }
    resid_ln_kernel<<<M_ROWS, 128>>>(xb, nullptr, lnf_g, lnf_b, 0);

    mma_gemm<1><<<dim3(512 / BN2, M_ROWS / BM2), 256>>>(xb, xm1_w, xm1_b, ab, M_ROWS, 512, 512);
    gemm_kernel<0><<<dim3(1, M_ROWS / BM), 256>>>(ab, xm2_w, xm2_b, zb, M_ROWS, 16, 512);
    gemm_kernel<1><<<dim3(512 / BN, M_ROWS / BM), 256>>>(zb, me1_w, me1_b, ab, M_ROWS, 512, 16);
    mma_gemm<1><<<dim3(512 / BN2, M_ROWS / BM2), 256>>>(ab, me2_w, me2_b, tb, M_ROWS, 512, 512);
    gemm_kernel<0><<<dim3(1, M_ROWS / BM), 256>>>(tb, me3_w, me3_b, yb, M_ROWS, 8, 512);

    zero_kernel<<<1, 1>>>((float*)d_out);
    loss_kernel<<<64, 256>>>(yb, y, (float*)d_out);
}

// round 6
// speedup vs baseline: 4.6986x; 1.6742x over previous
#include <cuda_runtime.h>
#include <math.h>

// ---------------- problem constants ----------------
#define B_SZ    4
#define T_SEQ   2048
#define M_ROWS  (B_SZ * T_SEQ)      // 8192
#define H_DIM   512
#define DFF     2048
#define NHEADS  4
#define DH      128
#define WIN     606
#define NLAYER  4
#define KTRUE   30

// ---------------- device scratch (no allocs allowed) ----------------
__device__ float g_x[M_ROWS * H_DIM];
__device__ float g_tmp[M_ROWS * DFF];
__device__ float g_attn[M_ROWS * H_DIM];
__device__ float g_z[M_ROWS * 16];
__device__ float g_yhat[M_ROWS * 8];

__device__ __forceinline__ float gelu_exact(float x) {
    return 0.5f * x * (1.0f + erff(x * 0.70710678118654752f));
}

// pack two fp32 into bf16x2 (round-to-nearest-even), pure integer math
__device__ __forceinline__ unsigned pk(float x, float y) {
    unsigned ux = __float_as_uint(x);
    unsigned uy = __float_as_uint(y);
    unsigned lo = (ux + 0x7FFFu + ((ux >> 16) & 1u)) >> 16;
    unsigned hi = (uy + 0x7FFFu + ((uy >> 16) & 1u)) >> 16;
    return lo | (hi << 16);
}

__device__ __forceinline__ unsigned smem_u32(const void* p) {
    unsigned a;
    asm("{ .reg .u64 t; cvta.to.shared.u64 t, %1; cvt.u32.u64 %0, t; }" : "=r"(a) : "l"(p));
    return a;
}
__device__ __forceinline__ void ldsm4(unsigned* r, unsigned addr) {
    asm volatile("ldmatrix.sync.aligned.m8n8.x4.shared.b16 {%0,%1,%2,%3}, [%4];"
                 : "=r"(r[0]), "=r"(r[1]), "=r"(r[2]), "=r"(r[3]) : "r"(addr));
}
__device__ __forceinline__ void ldsm4t(unsigned* r, unsigned addr) {
    asm volatile("ldmatrix.sync.aligned.m8n8.x4.trans.shared.b16 {%0,%1,%2,%3}, [%4];"
                 : "=r"(r[0]), "=r"(r[1]), "=r"(r[2]), "=r"(r[3]) : "r"(addr));
}
__device__ __forceinline__ void mma16816(float* d, const unsigned* a, const unsigned* b) {
    asm volatile(
        "mma.sync.aligned.m16n8k16.row.col.f32.bf16.bf16.f32 "
        "{%0,%1,%2,%3}, {%4,%5,%6,%7}, {%8,%9}, {%0,%1,%2,%3};"
        : "+f"(d[0]), "+f"(d[1]), "+f"(d[2]), "+f"(d[3])
        : "r"(a[0]), "r"(a[1]), "r"(a[2]), "r"(a[3]), "r"(b[0]), "r"(b[1]));
}

// ---------------- embedding ----------------
__global__ void embed_kernel(const float* __restrict__ u, const float* __restrict__ y,
                             const float* __restrict__ Win, const float* __restrict__ bin,
                             float* __restrict__ x) {
    int row = blockIdx.x;
    int b = row >> 11, t = row & 2047;
    bool yt = (t < KTRUE);
    float uv[8], yv[8];
#pragma unroll
    for (int c = 0; c < 8; c++) {
        uv[c] = u[((b * 8 + c) << 11) + t];
        yv[c] = yt ? y[((b * 8 + c) << 11) + t] : 0.0f;
    }
    int col = threadIdx.x * 4;
#pragma unroll
    for (int j = 0; j < 4; j++) {
        int cj = col + j;
        float s = bin[cj];
#pragma unroll
        for (int c = 0; c < 8; c++) s += uv[c] * Win[c * H_DIM + cj];
        if (yt) {
#pragma unroll
            for (int c = 0; c < 8; c++) s += yv[c] * Win[(16 + c) * H_DIM + cj];
        }
        float freq = expf(-(float)(cj & ~1) * (9.210340371976184f / 512.0f));
        float ang = (float)t * freq;
        s += (cj & 1) ? cosf(ang) : sinf(ang);
        x[(size_t)row * H_DIM + cj] = s;
    }
}

// ---------------- fp32 GEMM (small N / small K cases) ----------------
#define BM 64
#define BN 64
#define BK 16

template <int ACT>
__global__ void __launch_bounds__(256) gemm_kernel(
    const float* __restrict__ A, const float* __restrict__ W,
    const float* __restrict__ bias, float* __restrict__ C,
    int M, int N, int K) {
    __shared__ float As[BK][BM + 4];
    __shared__ float Ws[BK][BN];
    int tid = threadIdx.x;
    int row0 = blockIdx.y * BM, col0 = blockIdx.x * BN;
    int tr = tid >> 4, tc = tid & 15;
    int a_m = tid >> 2, a_k = (tid & 3) << 2;
    int w_k = tid >> 4, w_n = (tid & 15) << 2;
    float acc[4][4] = {};

    for (int k0 = 0; k0 < K; k0 += BK) {
        float4 av = *(const float4*)&A[(size_t)(row0 + a_m) * K + k0 + a_k];
        As[a_k + 0][a_m] = av.x;
        As[a_k + 1][a_m] = av.y;
        As[a_k + 2][a_m] = av.z;
        As[a_k + 3][a_m] = av.w;
#pragma unroll
        for (int j = 0; j < 4; j++) {
            int n = col0 + w_n + j;
            Ws[w_k][w_n + j] = (n < N) ? W[(size_t)(k0 + w_k) * N + n] : 0.0f;
        }
        __syncthreads();
#pragma unroll
        for (int kk = 0; kk < BK; kk++) {
            float4 a4 = *(const float4*)&As[kk][tr << 2];
            float4 w4 = *(const float4*)&Ws[kk][tc << 2];
            acc[0][0] += a4.x * w4.x; acc[0][1] += a4.x * w4.y; acc[0][2] += a4.x * w4.z; acc[0][3] += a4.x * w4.w;
            acc[1][0] += a4.y * w4.x; acc[1][1] += a4.y * w4.y; acc[1][2] += a4.y * w4.z; acc[1][3] += a4.y * w4.w;
            acc[2][0] += a4.z * w4.x; acc[2][1] += a4.z * w4.y; acc[2][2] += a4.z * w4.z; acc[2][3] += a4.z * w4.w;
            acc[3][0] += a4.w * w4.x; acc[3][1] += a4.w * w4.y; acc[3][2] += a4.w * w4.z; acc[3][3] += a4.w * w4.w;
        }
        __syncthreads();
    }
#pragma unroll
    for (int i = 0; i < 4; i++) {
        int row = row0 + (tr << 2) + i;
#pragma unroll
        for (int j = 0; j < 4; j++) {
            int cn = col0 + (tc << 2) + j;
            if (cn < N) {
                float v = acc[i][j] + bias[cn];
                if (ACT == 1) v = gelu_exact(v);
                C[(size_t)row * N + cn] = v;
            }
        }
    }
}

// ---------------- bf16 tensor-core GEMM ----------------
#define BM2 128
#define BN2 128
#define BK2 32
#define A_LD 40
#define B_LD 136

template <int ACT>
__global__ void __launch_bounds__(256) mma_gemm(
    const float* __restrict__ A, const float* __restrict__ W,
    const float* __restrict__ bias, float* __restrict__ C,
    int M, int N, int K) {
    __shared__ unsigned short As[2][BM2 * A_LD];
    __shared__ unsigned short Bs[2][BK2 * B_LD];
    int tid = threadIdx.x, lane = tid & 31, w = tid >> 5;
    int wm = (w & 1) * 64, wn = (w >> 1) * 32;
    int row0 = blockIdx.y * BM2, col0 = blockIdx.x * BN2;

    int aRow = tid >> 3, aK = (tid & 7) << 2;
    int bRow = tid >> 5, bCol = (tid & 31) << 2;

    float acc[4][4][4];
#pragma unroll
    for (int i = 0; i < 4; i++)
#pragma unroll
        for (int j = 0; j < 4; j++)
#pragma unroll
            for (int k = 0; k < 4; k++) acc[i][j][k] = 0.0f;

    uint2 aReg[4], bReg[4];
    int ktiles = K / BK2;

    {
        const float* Ab = A + (size_t)row0 * K + aK;
        const float* Wb = W + col0 + bCol;
#pragma unroll
        for (int j = 0; j < 4; j++) {
            float4 v = *(const float4*)(Ab + (size_t)(aRow + 32 * j) * K);
            aReg[j].x = pk(v.x, v.y);
            aReg[j].y = pk(v.z, v.w);
        }
#pragma unroll
        for (int j = 0; j < 4; j++) {
            float4 v = *(const float4*)(Wb + (size_t)(bRow + 8 * j) * N);
            bReg[j].x = pk(v.x, v.y);
            bReg[j].y = pk(v.z, v.w);
        }
    }
#pragma unroll
    for (int j = 0; j < 4; j++)
        *(uint2*)&As[0][(aRow + 32 * j) * A_LD + aK] = aReg[j];
#pragma unroll
    for (int j = 0; j < 4; j++)
        *(uint2*)&Bs[0][(bRow + 8 * j) * B_LD + bCol] = bReg[j];
    __syncthreads();

    for (int kt = 0; kt < ktiles; kt++) {
        int s = kt & 1;
        if (kt + 1 < ktiles) {
            const float* Ab = A + (size_t)row0 * K + (kt + 1) * BK2 + aK;
            const float* Wb = W + (size_t)((kt + 1) * BK2) * N + col0 + bCol;
#pragma unroll
            for (int j = 0; j < 4; j++) {
                float4 v = *(const float4*)(Ab + (size_t)(aRow + 32 * j) * K);
                aReg[j].x = pk(v.x, v.y);
                aReg[j].y = pk(v.z, v.w);
            }
#pragma unroll
            for (int j = 0; j < 4; j++) {
                float4 v = *(const float4*)(Wb + (size_t)(bRow + 8 * j) * N);
                bReg[j].x = pk(v.x, v.y);
                bReg[j].y = pk(v.z, v.w);
            }
        }
        unsigned aBase = smem_u32(&As[s][0]);
        unsigned bBase = smem_u32(&Bs[s][0]);
#pragma unroll
        for (int ks = 0; ks < 2; ks++) {
            unsigned af[4][4];
#pragma unroll
            for (int mt = 0; mt < 4; mt++)
                ldsm4(af[mt], aBase + 2u * (unsigned)((wm + mt * 16 + (lane & 15)) * A_LD +
                                                      ks * 16 + (lane >> 4) * 8));
            unsigned bf[2][4];
#pragma unroll
            for (int nb = 0; nb < 2; nb++)
                ldsm4t(bf[nb], bBase + 2u * (unsigned)((ks * 16 + (lane & 15)) * B_LD +
                                                       wn + nb * 16 + (lane >> 4) * 8));
#pragma unroll
            for (int mt = 0; mt < 4; mt++) {
#pragma unroll
                for (int nt = 0; nt < 4; nt++) {
                    unsigned bb[2];
                    bb[0] = bf[nt >> 1][(nt & 1) * 2];
                    bb[1] = bf[nt >> 1][(nt & 1) * 2 + 1];
                    mma16816(acc[mt][nt], af[mt], bb);
                }
            }
        }
        __syncthreads();
        if (kt + 1 < ktiles) {
#pragma unroll
            for (int j = 0; j < 4; j++)
                *(uint2*)&As[1 - s][(aRow + 32 * j) * A_LD + aK] = aReg[j];
#pragma unroll
            for (int j = 0; j < 4; j++)
                *(uint2*)&Bs[1 - s][(bRow + 8 * j) * B_LD + bCol] = bReg[j];
            __syncthreads();
        }
    }

#pragma unroll
    for (int mt = 0; mt < 4; mt++) {
#pragma unroll
        for (int nt = 0; nt < 4; nt++) {
            int r = row0 + wm + mt * 16 + (lane >> 2);
            int c = col0 + wn + nt * 8 + (lane & 3) * 2;
            float b0 = bias[c], b1 = bias[c + 1];
            float v0 = acc[mt][nt][0] + b0, v1 = acc[mt][nt][1] + b1;
            float v2 = acc[mt][nt][2] + b0, v3 = acc[mt][nt][3] + b1;
            if (ACT == 1) {
                v0 = gelu_exact(v0); v1 = gelu_exact(v1);
                v2 = gelu_exact(v2); v3 = gelu_exact(v3);
            }
            *(float2*)&C[(size_t)r * N + c] = make_float2(v0, v1);
            *(float2*)&C[(size_t)(r + 8) * N + c] = make_float2(v2, v3);
        }
    }
}

// ---------------- tensor-core sliding-window flash attention ----------------
// qkv: [M,1536]; block 128 thr (4 warps), warp w owns q-rows [16w,16w+16).
// TQ=TK=64. Q/K/V bf16 in smem, row stride 136 (272B -> conflict-free ldmatrix).
#define AQ_LD 136
#define ATTN_SMEM_BYTES (3 * 64 * AQ_LD * 2)

__global__ void __launch_bounds__(128) attn_mma_kernel(const float* __restrict__ qkv,
                                                       float* __restrict__ o) {
    extern __shared__ unsigned short sma[];
    unsigned short* Qs = sma;                 // [64][136]
    unsigned short* Ks = Qs + 64 * AQ_LD;     // [64][136] (rows = keys, cols = dims)
    unsigned short* Vs = Ks + 64 * AQ_LD;     // [64][136] (rows = dims-k, cols... rows = keys)

    int tid = threadIdx.x, lane = tid & 31, w = tid >> 5;
    int qt = blockIdx.x, hd = blockIdx.y, b = blockIdx.z;
    int q0 = qt * 64;
    const float scale = 0.088388347648318447f;  // 1/sqrt(128)
    size_t base = (size_t)(b * T_SEQ) * 1536 + hd * DH;

    // load Q (scaled) -> bf16 smem
    for (int idx = tid; idx < 64 * 32; idx += 128) {
        int r = idx >> 5, c = idx & 31;
        float4 v = *(const float4*)&qkv[base + (size_t)(q0 + r) * 1536 + (c << 2)];
        uint2 p;
        p.x = pk(v.x * scale, v.y * scale);
        p.y = pk(v.z * scale, v.w * scale);
        *(uint2*)&Qs[r * AQ_LD + (c << 2)] = p;
    }

    float oa[16][4];
#pragma unroll
    for (int i = 0; i < 16; i++)
#pragma unroll
        for (int j = 0; j < 4; j++) oa[i][j] = 0.0f;
    float m0 = -1e30f, m1 = -1e30f, l0 = 0.0f, l1 = 0.0f;

    int r0 = q0 + 16 * w + (lane >> 2);
    int r1 = r0 + 8;

    int lo = q0 - (WIN - 1);
    if (lo < 0) lo = 0;
    unsigned qBase = smem_u32(Qs);
    unsigned kBase = smem_u32(Ks);
    unsigned vBase = smem_u32(Vs);

    for (int kt = lo >> 6; kt <= qt; kt++) {
        int k0 = kt * 64;
        __syncthreads();
        // load K, V tiles
        for (int idx = tid; idx < 64 * 32; idx += 128) {
            int r = idx >> 5, c = idx & 31;
            size_t rb = base + (size_t)(k0 + r) * 1536 + (c << 2);
            float4 kv = *(const float4*)&qkv[rb + 512];
            float4 vv = *(const float4*)&qkv[rb + 1024];
            uint2 pK, pV;
            pK.x = pk(kv.x, kv.y); pK.y = pk(kv.z, kv.w);
            pV.x = pk(vv.x, vv.y); pV.y = pk(vv.z, vv.w);
            *(uint2*)&Ks[r * AQ_LD + (c << 2)] = pK;
            *(uint2*)&Vs[r * AQ_LD + (c << 2)] = pV;
        }
        __syncthreads();

        // S = Q K^T : 8 n-tiles (keys), 8 k-steps (dims)
        float sc[8][4];
#pragma unroll
        for (int t = 0; t < 8; t++)
#pragma unroll
            for (int e = 0; e < 4; e++) sc[t][e] = 0.0f;

#pragma unroll
        for (int ks = 0; ks < 8; ks++) {
            unsigned aq[4];
            ldsm4(aq, qBase + 2u * (unsigned)((16 * w + (lane & 15)) * AQ_LD +
                                              ks * 16 + (lane >> 4) * 8));
#pragma unroll
            for (int np = 0; np < 4; np++) {
                unsigned bk[4];
                // rows = keys (n-major): non-trans ldmatrix gives col-major B frags
                ldsm4(bk, kBase + 2u * (unsigned)((np * 16 + (lane & 7) + ((lane >> 4) & 1) * 8) * AQ_LD +
                                                  ks * 16 + ((lane >> 3) & 1) * 8));
                unsigned bb[2];
                bb[0] = bk[0]; bb[1] = bk[1];
                mma16816(sc[2 * np], aq, bb);
                bb[0] = bk[2]; bb[1] = bk[3];
                mma16816(sc[2 * np + 1], aq, bb);
            }
        }

        // mask (only on edge tiles)
        bool full = (k0 + 63 <= q0) && (k0 > q0 + 63 - WIN);
        if (!full) {
#pragma unroll
            for (int t = 0; t < 8; t++) {
                int c0 = k0 + 8 * t + ((lane & 3) << 1);
                int c1 = c0 + 1;
                if (!(c0 <= r0 && c0 > r0 - WIN)) sc[t][0] = -1e30f;
                if (!(c1 <= r0 && c1 > r0 - WIN)) sc[t][1] = -1e30f;
                if (!(c0 <= r1 && c0 > r1 - WIN)) sc[t][2] = -1e30f;
                if (!(c1 <= r1 && c1 > r1 - WIN)) sc[t][3] = -1e30f;
            }
        }

        // online softmax
        float tm0 = -1e30f, tm1 = -1e30f;
#pragma unroll
        for (int t = 0; t < 8; t++) {
            tm0 = fmaxf(tm0, fmaxf(sc[t][0], sc[t][1]));
            tm1 = fmaxf(tm1, fmaxf(sc[t][2], sc[t][3]));
        }
        tm0 = fmaxf(tm0, __shfl_xor_sync(0xffffffffu, tm0, 1));
        tm0 = fmaxf(tm0, __shfl_xor_sync(0xffffffffu, tm0, 2));
        tm1 = fmaxf(tm1, __shfl_xor_sync(0xffffffffu, tm1, 1));
        tm1 = fmaxf(tm1, __shfl_xor_sync(0xffffffffu, tm1, 2));
        float mn0 = fmaxf(m0, tm0), mn1 = fmaxf(m1, tm1);
        float sc0 = __expf(m0 - mn0), sc1 = __expf(m1 - mn1);
        float rs0 = 0.0f, rs1 = 0.0f;
#pragma unroll
        for (int t = 0; t < 8; t++) {
            sc[t][0] = __expf(sc[t][0] - mn0);
            sc[t][1] = __expf(sc[t][1] - mn0);
            sc[t][2] = __expf(sc[t][2] - mn1);
            sc[t][3] = __expf(sc[t][3] - mn1);
            rs0 += sc[t][0] + sc[t][1];
            rs1 += sc[t][2] + sc[t][3];
        }
        rs0 += __shfl_xor_sync(0xffffffffu, rs0, 1);
        rs0 += __shfl_xor_sync(0xffffffffu, rs0, 2);
        rs1 += __shfl_xor_sync(0xffffffffu, rs1, 1);
        rs1 += __shfl_xor_sync(0xffffffffu, rs1, 2);
        l0 = l0 * sc0 + rs0;
        l1 = l1 * sc1 + rs1;
        m0 = mn0; m1 = mn1;
#pragma unroll
        for (int t = 0; t < 16; t++) {
            oa[t][0] *= sc0; oa[t][1] *= sc0;
            oa[t][2] *= sc1; oa[t][3] *= sc1;
        }

        // O += P @ V : k-steps over 64 keys, n over 128 dims
#pragma unroll
        for (int kk = 0; kk < 4; kk++) {
            unsigned ap[4];
            ap[0] = pk(sc[2 * kk][0], sc[2 * kk][1]);
            ap[1] = pk(sc[2 * kk][2], sc[2 * kk][3]);
            ap[2] = pk(sc[2 * kk + 1][0], sc[2 * kk + 1][1]);
            ap[3] = pk(sc[2 * kk + 1][2], sc[2 * kk + 1][3]);
#pragma unroll
            for (int nt = 0; nt < 8; nt++) {
                unsigned bv[4];
                ldsm4t(bv, vBase + 2u * (unsigned)((kk * 16 + (lane & 15)) * AQ_LD +
                                                   nt * 16 + (lane >> 4) * 8));
                unsigned bb[2];
                bb[0] = bv[0]; bb[1] = bv[1];
                mma16816(oa[2 * nt], ap, bb);
                bb[0] = bv[2]; bb[1] = bv[3];
                mma16816(oa[2 * nt + 1], ap, bb);
            }
        }
    }

    // epilogue: normalize and store
    float inv0 = 1.0f / l0, inv1 = 1.0f / l1;
    size_t ob = (size_t)(b * T_SEQ) * H_DIM + hd * DH;
#pragma unroll
    for (int t = 0; t < 16; t++) {
        int c = 8 * t + ((lane & 3) << 1);
        *(float2*)&o[ob + (size_t)r0 * H_DIM + c] = make_float2(oa[t][0] * inv0, oa[t][1] * inv0);
        *(float2*)&o[ob + (size_t)r1 * H_DIM + c] = make_float2(oa[t][2] * inv1, oa[t][3] * inv1);
    }
}

// ---------------- residual + layernorm ----------------
__global__ void resid_ln_kernel(float* __restrict__ x, const float* __restrict__ p,
                                const float* __restrict__ g, const float* __restrict__ bb,
                                int has_res) {
    __shared__ float red[8];
    int row = blockIdx.x, tid = threadIdx.x;
    int c = tid * 4;
    float4 v = *(float4*)&x[(size_t)row * H_DIM + c];
    if (has_res) {
        float4 pv = *(const float4*)&p[(size_t)row * H_DIM + c];
        v.x += pv.x; v.y += pv.y; v.z += pv.z; v.w += pv.w;
    }
    float s = v.x + v.y + v.z + v.w;
    float q = v.x * v.x + v.y * v.y + v.z * v.z + v.w * v.w;
    int lane = tid & 31, wp = tid >> 5;
#pragma unroll
    for (int off = 16; off; off >>= 1) s += __shfl_xor_sync(0xffffffffu, s, off);
    if (lane == 0) red[wp] = s;
    __syncthreads();
    float s_tot = red[0] + red[1] + red[2] + red[3];
    __syncthreads();
#pragma unroll
    for (int off = 16; off; off >>= 1) q += __shfl_xor_sync(0xffffffffu, q, off);
    if (lane == 0) red[wp] = q;
    __syncthreads();
    float q_tot = red[0] + red[1] + red[2] + red[3];

    float mean = s_tot * (1.0f / 512.0f);
    float var = q_tot * (1.0f / 512.0f) - mean * mean;
    float inv = rsqrtf(var + 1e-5f);
    float4 ov;
    ov.x = (v.x - mean) * inv * g[c + 0] + bb[c + 0];
    ov.y = (v.y - mean) * inv * g[c + 1] + bb[c + 1];
    ov.z = (v.z - mean) * inv * g[c + 2] + bb[c + 2];
    ov.w = (v.w - mean) * inv * g[c + 3] + bb[c + 3];
    *(float4*)&x[(size_t)row * H_DIM + c] = ov;
}

// ---------------- loss ----------------
__global__ void zero_kernel(float* o) { o[0] = 0.0f; }

__global__ void loss_kernel(const float* __restrict__ yhat, const float* __restrict__ y,
                            float* __restrict__ o) {
    __shared__ float red[8];
    int tid = threadIdx.x;
    float s = 0.0f;
    for (int idx = blockIdx.x * 256 + tid; idx < M_ROWS * 8; idx += gridDim.x * 256) {
        int row = idx >> 3, c = idx & 7;
        int b = row >> 11, t = row & 2047;
        float d = yhat[idx] - y[((b * 8 + c) << 11) + t];
        s += d * d;
    }
    int lane = tid & 31, wp = tid >> 5;
#pragma unroll
    for (int off = 16; off; off >>= 1) s += __shfl_xor_sync(0xffffffffu, s, off);
    if (lane == 0) red[wp] = s;
    __syncthreads();
    if (tid == 0) {
        float t2 = 0.0f;
        for (int i = 0; i < 8; i++) t2 += red[i];
        atomicAdd(o, t2);
    }
}

// ---------------- launch ----------------
extern "C" void kernel_launch(void* const* d_in, const int* in_sizes, int n_in,
                              void* d_out, int out_size) {
    const float* u     = (const float*)d_in[0];
    const float* y     = (const float*)d_in[1];
    const float* W_in  = (const float*)d_in[2];
    const float* b_in  = (const float*)d_in[3];
    const float* qkv_w = (const float*)d_in[4];
    const float* qkv_b = (const float*)d_in[5];
    const float* out_w = (const float*)d_in[6];
    const float* out_b = (const float*)d_in[7];
    const float* ff1_w = (const float*)d_in[8];
    const float* ff1_b = (const float*)d_in[9];
    const float* ff2_w = (const float*)d_in[10];
    const float* ff2_b = (const float*)d_in[11];
    const float* ln1_g = (const float*)d_in[12];
    const float* ln1_b = (const float*)d_in[13];
    const float* ln2_g = (const float*)d_in[14];
    const float* ln2_b = (const float*)d_in[15];
    const float* lnf_g = (const float*)d_in[16];
    const float* lnf_b = (const float*)d_in[17];
    const float* xm1_w = (const float*)d_in[18];
    const float* xm1_b = (const float*)d_in[19];
    const float* xm2_w = (const float*)d_in[20];
    const float* xm2_b = (const float*)d_in[21];
    const float* me1_w = (const float*)d_in[22];
    const float* me1_b = (const float*)d_in[23];
    const float* me2_w = (const float*)d_in[24];
    const float* me2_b = (const float*)d_in[25];
    const float* me3_w = (const float*)d_in[26];
    const float* me3_b = (const float*)d_in[27];

    float *xb, *tb, *ab, *zb, *yb;
    cudaGetSymbolAddress((void**)&xb, g_x);
    cudaGetSymbolAddress((void**)&tb, g_tmp);
    cudaGetSymbolAddress((void**)&ab, g_attn);
    cudaGetSymbolAddress((void**)&zb, g_z);
    cudaGetSymbolAddress((void**)&yb, g_yhat);

    cudaFuncSetAttribute(attn_mma_kernel, cudaFuncAttributeMaxDynamicSharedMemorySize,
                         ATTN_SMEM_BYTES);

    embed_kernel<<<M_ROWS, 128>>>(u, y, W_in, b_in, xb);

    for (int l = 0; l < NLAYER; l++) {
        mma_gemm<0><<<dim3(1536 / BN2, M_ROWS / BM2), 256>>>(
            xb, qkv_w + (size_t)l * 512 * 1536, qkv_b + (size_t)l * 1536, tb,
            M_ROWS, 1536, 512);
        attn_mma_kernel<<<dim3(T_SEQ / 64, NHEADS, B_SZ), 128, ATTN_SMEM_BYTES>>>(tb, ab);
        mma_gemm<0><<<dim3(512 / BN2, M_ROWS / BM2), 256>>>(
            ab, out_w + (size_t)l * 512 * 512, out_b + (size_t)l * 512, tb,
            M_ROWS, 512, 512);
        resid_ln_kernel<<<M_ROWS, 128>>>(xb, tb, ln1_g + l * 512, ln1_b + l * 512, 1);
        mma_gemm<1><<<dim3(2048 / BN2, M_ROWS / BM2), 256>>>(
            xb, ff1_w + (size_t)l * 512 * 2048, ff1_b + (size_t)l * 2048, tb,
            M_ROWS, 2048, 512);
        mma_gemm<0><<<dim3(512 / BN2, M_ROWS / BM2), 256>>>(
            tb, ff2_w + (size_t)l * 2048 * 512, ff2_b + (size_t)l * 512, ab,
            M_ROWS, 512, 2048);
        resid_ln_kernel<<<M_ROWS, 128>>>(xb, ab, ln2_g + l * 512, ln2_b + l * 512, 1);
    }
    resid_ln_kernel<<<M_ROWS, 128>>>(xb, nullptr, lnf_g, lnf_b, 0);

    mma_gemm<1><<<dim3(512 / BN2, M_ROWS / BM2), 256>>>(xb, xm1_w, xm1_b, ab, M_ROWS, 512, 512);
    gemm_kernel<0><<<dim3(1, M_ROWS / BM), 256>>>(ab, xm2_w, xm2_b, zb, M_ROWS, 16, 512);
    gemm_kernel<1><<<dim3(512 / BN, M_ROWS / BM), 256>>>(zb, me1_w, me1_b, ab, M_ROWS, 512, 16);
    mma_gemm<1><<<dim3(512 / BN2, M_ROWS / BM2), 256>>>(ab, me2_w, me2_b, tb, M_ROWS, 512, 512);
    gemm_kernel<0><<<dim3(1, M_ROWS / BM), 256>>>(tb, me3_w, me3_b, yb, M_ROWS, 8, 512);

    zero_kernel<<<1, 1>>>((float*)d_out);
    loss_kernel<<<64, 256>>>(yb, y, (float*)d_out);
}